// round 11
// baseline (speedup 1.0000x reference)
#include <cuda_runtime.h>
#include <cuda_bf16.h>
#include <cstdint>

// S4D Vandermonde kernel.
// out[h, l] = 2 * Re( sum_n Ceff[h,n] * exp(dtA[h,n] * l) ),  l in [0, L)
//
// R9 (ALU path; tcgen05 blocked by harness PTX target compute_103 w/o 'a'):
//  - Chebyshev-style real 2-term recurrence: y_{k+1} = t*y_k - d*y_{k-1},
//    t = 2*Re(w), d = |w|^2, w = exp(dtA*2*BT). 3 packed f32x2 ops / 2 outputs.
//  - NEW: per-block shared start-state table S[n][tid] = Ceff2*exp(dtA*(base+tid)),
//    built once (32 sincos/exp per thread); the per-pair resync becomes 2x LDS.64.
//  - NEW: per-pair coefficients pre-packed into u64 smem (1 LDS.64 each).
// Thread t of a BT-thread block covers l = base + j*BT + t (coalesced stores).

#define BT 128   // threads per block
#define TL 32    // l-values per thread (register accumulators)
#define MAXNH 64
#define TBL_NH 32

typedef unsigned long long u64;

__device__ __forceinline__ u64 pack2(float lo, float hi) {
    u64 d; asm("mov.b64 %0, {%1, %2};" : "=l"(d) : "f"(lo), "f"(hi)); return d;
}
__device__ __forceinline__ float2 unpack2(u64 v) {
    float2 f; asm("mov.b64 {%0, %1}, %2;" : "=f"(f.x), "=f"(f.y) : "l"(v)); return f;
}
__device__ __forceinline__ u64 mul2(u64 a, u64 b) {
    u64 d; asm("mul.rn.f32x2 %0, %1, %2;" : "=l"(d) : "l"(a), "l"(b)); return d;
}
__device__ __forceinline__ u64 add2(u64 a, u64 b) {
    u64 d; asm("add.rn.f32x2 %0, %1, %2;" : "=l"(d) : "l"(a), "l"(b)); return d;
}
__device__ __forceinline__ u64 fma2(u64 a, u64 b, u64 c) {
    u64 d; asm("fma.rn.f32x2 %0, %1, %2, %3;" : "=l"(d) : "l"(a), "l"(b), "l"(c)); return d;
}

// ════════════════════════════════════════════════════════════════════════
// Fast path: NH == 32, shared start-state table
// ════════════════════════════════════════════════════════════════════════
__global__ __launch_bounds__(BT)
void s4d_tbl_kernel(const float* __restrict__ Cp,
                    const float* __restrict__ log_dt,
                    const float* __restrict__ log_A_real,
                    const float* __restrict__ A_imag,
                    float* __restrict__ out,
                    int L)
{
    __shared__ float        sh_dtAre[TBL_NH];
    __shared__ unsigned int sh_P[TBL_NH];
    __shared__ float        sh_C2re[TBL_NH], sh_C2im[TBL_NH];
    __shared__ float        sh_Rre[TBL_NH],  sh_Rim[TBL_NH];
    __shared__ float        sh_R2re[TBL_NH], sh_R2im[TBL_NH];
    __shared__ float        sh_T2[TBL_NH],   sh_ND2[TBL_NH];
    __shared__ u64          pk_rre[TBL_NH/2],  pk_rim[TBL_NH/2], pk_nrim[TBL_NH/2];
    __shared__ u64          pk_r2re[TBL_NH/2], pk_nr2im[TBL_NH/2];
    __shared__ u64          pk_t2[TBL_NH/2],   pk_nd2[TBL_NH/2];
    __shared__ float2       sh_S[TBL_NH][BT];   // start states, 32 KB

    const int h    = blockIdx.y;
    const int tid  = threadIdx.x;
    const int base = blockIdx.x * (BT * TL);

    // ---- per-(h,n) scalar precompute ----
    if (tid < TBL_NH) {
        const int n = tid;
        const float dtv   = expf(log_dt[h]);
        const float Aim   = A_imag[h * TBL_NH + n];
        const float Are   = -expf(log_A_real[h * TBL_NH + n]);
        const float dtAre = Are * dtv;
        const float dtAim = Aim * dtv;

        float sn1, cs1; sincosf(dtAim, &sn1, &cs1);
        const float mg  = expf(dtAre);
        const float er  = mg * cs1 - 1.0f;
        const float ei  = mg * sn1;
        const float inv = 1.0f / (Are * Are + Aim * Aim);
        const float qre = (er * Are + ei * Aim) * inv;
        const float qim = (ei * Are - er * Aim) * inv;
        const float Cre = Cp[(h * TBL_NH + n) * 2 + 0];
        const float Cim = Cp[(h * TBL_NH + n) * 2 + 1];
        sh_C2re[n] = 2.0f * (Cre * qre - Cim * qim);
        sh_C2im[n] = 2.0f * (Cre * qim + Cim * qre);
        {
            double f  = (double)dtAim * 0.15915494309189535;
            double fr = f - floor(f);
            sh_P[n] = (unsigned int)(unsigned long long)(fr * 4294967296.0 + 0.5);
        }
        {
            float sp, cp2; sincosf(dtAim * (float)BT, &sp, &cp2);
            const float Rm = expf(dtAre * (float)BT);
            sh_Rre[n] = Rm * cp2;  sh_Rim[n] = Rm * sp;
        }
        {
            float sp, cp2; sincosf(dtAim * (float)(2 * BT), &sp, &cp2);
            const float Rm = expf(dtAre * (float)(2 * BT));
            sh_R2re[n] = Rm * cp2;  sh_R2im[n] = Rm * sp;
            sh_T2[n]   = 2.0f * Rm * cp2;
            sh_ND2[n]  = -expf(dtAre * (float)(4 * BT));
        }
        sh_dtAre[n] = dtAre;
    }
    __syncthreads();

    // ---- pack per-pair coefficients (threads 0..15) ----
    if (tid < TBL_NH / 2) {
        const int nA = 2 * tid, nB = 2 * tid + 1;
        pk_rre[tid]   = pack2(sh_Rre[nA],   sh_Rre[nB]);
        pk_rim[tid]   = pack2(sh_Rim[nA],   sh_Rim[nB]);
        pk_nrim[tid]  = pack2(-sh_Rim[nA],  -sh_Rim[nB]);
        pk_r2re[tid]  = pack2(sh_R2re[nA],  sh_R2re[nB]);
        pk_nr2im[tid] = pack2(-sh_R2im[nA], -sh_R2im[nB]);
        pk_t2[tid]    = pack2(sh_T2[nA],    sh_T2[nB]);
        pk_nd2[tid]   = pack2(sh_ND2[nA],   sh_ND2[nB]);
    }

    // ---- build start-state table: S[n][tid] = Ceff2[n] * exp(dtA[n]*(base+tid)) ----
    {
        const unsigned int l0u = (unsigned int)(base + tid);
        const float        l0f = (float)(base + tid);
        const float TWO_PI_OVER_2_32 = 1.4629180792671596e-9f;
        #pragma unroll 4
        for (int n = 0; n < TBL_NH; n++) {
            float th = (float)(int)(sh_P[n] * l0u) * TWO_PI_OVER_2_32;  // [-pi, pi)
            float sn, cs; __sincosf(th, &sn, &cs);
            float m  = __expf(sh_dtAre[n] * l0f);
            float cr = sh_C2re[n], ci = sh_C2im[n];
            sh_S[n][tid] = make_float2(m * (cr * cs - ci * sn),
                                       m * (cr * sn + ci * cs));
        }
    }
    __syncthreads();

    u64 acc[TL];
    #pragma unroll
    for (int j = 0; j < TL; j++) acc[j] = 0ull;

    // ---- main loop over n-pairs: resync = 2x LDS.64 + a few packed ops ----
    #pragma unroll 2
    for (int p = 0; p < TBL_NH / 2; p++) {
        const float2 sA = sh_S[2 * p][tid];
        const float2 sB = sh_S[2 * p + 1][tid];
        u64 se_re = pack2(sA.x, sB.x);
        u64 se_im = pack2(sA.y, sB.y);

        // odd stream start: so = se * R(BT)
        const u64 rre  = pk_rre[p];
        const u64 rim  = pk_rim[p];
        const u64 nrim = pk_nrim[p];
        u64 so_re = fma2(se_im, nrim, mul2(se_re, rre));
        u64 so_im = fma2(se_im, rre,  mul2(se_re, rim));

        // y1 per stream: Re(s * R2)
        const u64 r2re  = pk_r2re[p];
        const u64 nr2im = pk_nr2im[p];
        u64 ye0 = se_re;
        u64 ye1 = fma2(se_im, nr2im, mul2(se_re, r2re));
        u64 yo0 = so_re;
        u64 yo1 = fma2(so_im, nr2im, mul2(so_re, r2re));

        const u64 t2  = pk_t2[p];
        const u64 nd2 = pk_nd2[p];

        acc[0] = add2(acc[0], ye0);
        acc[1] = add2(acc[1], yo0);
        acc[2] = add2(acc[2], ye1);
        acc[3] = add2(acc[3], yo1);

        // y_{k+1} = t*y_k + (-d)*y_{k-1}; 3 packed ops per step per stream
        #pragma unroll
        for (int k = 2; k < TL / 2; k++) {
            u64 ye2 = fma2(t2, ye1, mul2(nd2, ye0));
            acc[2 * k] = add2(acc[2 * k], ye2);
            ye0 = ye1; ye1 = ye2;

            u64 yo2 = fma2(t2, yo1, mul2(nd2, yo0));
            acc[2 * k + 1] = add2(acc[2 * k + 1], yo2);
            yo0 = yo1; yo1 = yo2;
        }
    }

    // ---- coalesced epilogue ----
    float* op = out + (size_t)h * (size_t)L;
    #pragma unroll
    for (int j = 0; j < TL; j++) {
        const int l = base + j * BT + tid;
        if (l < L) {
            float2 f = unpack2(acc[j]);
            op[l] = f.x + f.y;
        }
    }
}

// ════════════════════════════════════════════════════════════════════════
// Fallback (generic NH): R6 kernel, proven at 37.3 us
// ════════════════════════════════════════════════════════════════════════
__global__ __launch_bounds__(BT)
void s4d_kernel(const float* __restrict__ Cp,
                const float* __restrict__ log_dt,
                const float* __restrict__ log_A_real,
                const float* __restrict__ A_imag,
                float* __restrict__ out,
                int NH, int L)
{
    __shared__ float        sh_dtAre[MAXNH];
    __shared__ unsigned int sh_P[MAXNH];
    __shared__ float        sh_C2re[MAXNH], sh_C2im[MAXNH];
    __shared__ float        sh_Rre[MAXNH],  sh_Rim[MAXNH];
    __shared__ float        sh_R2re[MAXNH], sh_R2im[MAXNH];
    __shared__ float        sh_T2[MAXNH],   sh_ND2[MAXNH];

    const int h    = blockIdx.y;
    const int tid  = threadIdx.x;
    const int base = blockIdx.x * (BT * TL);

    if (tid < NH) {
        const int n = tid;
        const float dtv   = expf(log_dt[h]);
        const float Aim   = A_imag[h * NH + n];
        const float Are   = -expf(log_A_real[h * NH + n]);
        const float dtAre = Are * dtv;
        const float dtAim = Aim * dtv;

        float sn1, cs1; sincosf(dtAim, &sn1, &cs1);
        const float mg  = expf(dtAre);
        const float er  = mg * cs1 - 1.0f;
        const float ei  = mg * sn1;
        const float inv = 1.0f / (Are * Are + Aim * Aim);
        const float qre = (er * Are + ei * Aim) * inv;
        const float qim = (ei * Are - er * Aim) * inv;
        const float Cre = Cp[(h * NH + n) * 2 + 0];
        const float Cim = Cp[(h * NH + n) * 2 + 1];
        sh_C2re[n] = 2.0f * (Cre * qre - Cim * qim);
        sh_C2im[n] = 2.0f * (Cre * qim + Cim * qre);
        {
            double f  = (double)dtAim * 0.15915494309189535;
            double fr = f - floor(f);
            sh_P[n] = (unsigned int)(unsigned long long)(fr * 4294967296.0 + 0.5);
        }
        {
            float sp, cp2; sincosf(dtAim * (float)BT, &sp, &cp2);
            const float Rm = expf(dtAre * (float)BT);
            sh_Rre[n] = Rm * cp2;  sh_Rim[n] = Rm * sp;
        }
        {
            float sp, cp2; sincosf(dtAim * (float)(2 * BT), &sp, &cp2);
            const float Rm = expf(dtAre * (float)(2 * BT));
            sh_R2re[n] = Rm * cp2;  sh_R2im[n] = Rm * sp;
            sh_T2[n]   = 2.0f * Rm * cp2;
            sh_ND2[n]  = -expf(dtAre * (float)(4 * BT));
        }
        sh_dtAre[n] = dtAre;
    }
    __syncthreads();

    u64 acc[TL];
    #pragma unroll
    for (int j = 0; j < TL; j++) acc[j] = 0ull;

    const unsigned int l0u = (unsigned int)(base + tid);
    const float        l0f = (float)(base + tid);
    const int npairs = NH >> 1;
    const float TWO_PI_OVER_2_32 = 1.4629180792671596e-9f;

    for (int p = 0; p < npairs; p++) {
        const int nA = 2 * p, nB = 2 * p + 1;
        float areA, aimA, areB, aimB;
        {
            float th = (float)(int)(sh_P[nA] * l0u) * TWO_PI_OVER_2_32;
            float sn, cs; __sincosf(th, &sn, &cs);
            float m  = __expf(sh_dtAre[nA] * l0f);
            float cr = sh_C2re[nA], ci = sh_C2im[nA];
            areA = m * (cr * cs - ci * sn);
            aimA = m * (cr * sn + ci * cs);
        }
        {
            float th = (float)(int)(sh_P[nB] * l0u) * TWO_PI_OVER_2_32;
            float sn, cs; __sincosf(th, &sn, &cs);
            float m  = __expf(sh_dtAre[nB] * l0f);
            float cr = sh_C2re[nB], ci = sh_C2im[nB];
            areB = m * (cr * cs - ci * sn);
            aimB = m * (cr * sn + ci * cs);
        }
        u64 se_re = pack2(areA, areB);
        u64 se_im = pack2(aimA, aimB);
        u64 rre  = pack2(sh_Rre[nA],   sh_Rre[nB]);
        u64 rim  = pack2(sh_Rim[nA],   sh_Rim[nB]);
        u64 nrim = pack2(-sh_Rim[nA],  -sh_Rim[nB]);
        u64 so_re = fma2(se_im, nrim, mul2(se_re, rre));
        u64 so_im = fma2(se_im, rre,  mul2(se_re, rim));
        u64 r2re  = pack2(sh_R2re[nA],  sh_R2re[nB]);
        u64 nr2im = pack2(-sh_R2im[nA], -sh_R2im[nB]);
        u64 ye0 = se_re;
        u64 ye1 = fma2(se_im, nr2im, mul2(se_re, r2re));
        u64 yo0 = so_re;
        u64 yo1 = fma2(so_im, nr2im, mul2(so_re, r2re));
        u64 t2  = pack2(sh_T2[nA],  sh_T2[nB]);
        u64 nd2 = pack2(sh_ND2[nA], sh_ND2[nB]);

        acc[0] = add2(acc[0], ye0);
        acc[1] = add2(acc[1], yo0);
        acc[2] = add2(acc[2], ye1);
        acc[3] = add2(acc[3], yo1);

        #pragma unroll
        for (int k = 2; k < TL / 2; k++) {
            u64 ye2 = fma2(t2, ye1, mul2(nd2, ye0));
            acc[2 * k] = add2(acc[2 * k], ye2);
            ye0 = ye1; ye1 = ye2;
            u64 yo2 = fma2(t2, yo1, mul2(nd2, yo0));
            acc[2 * k + 1] = add2(acc[2 * k + 1], yo2);
            yo0 = yo1; yo1 = yo2;
        }
    }

    float* op = out + (size_t)h * (size_t)L;
    #pragma unroll
    for (int j = 0; j < TL; j++) {
        const int l = base + j * BT + tid;
        if (l < L) {
            float2 f = unpack2(acc[j]);
            op[l] = f.x + f.y;
        }
    }
}

// ════════════════════════════════════════════════════════════════════════
extern "C" void kernel_launch(void* const* d_in, const int* in_sizes, int n_in,
                              void* d_out, int out_size) {
    const float* Cp         = (const float*)d_in[0];  // (H, NH, 2)
    const float* log_dt     = (const float*)d_in[1];  // (H,)
    const float* log_A_real = (const float*)d_in[2];  // (H, NH)
    const float* A_imag     = (const float*)d_in[3];  // (H, NH)
    float* out = (float*)d_out;                       // (H, L)

    const int H  = in_sizes[1];
    const int NH = in_sizes[2] / H;
    const int L  = out_size / H;

    const int chunk = BT * TL;
    dim3 grid((L + chunk - 1) / chunk, H);
    if (NH == TBL_NH) {
        s4d_tbl_kernel<<<grid, BT>>>(Cp, log_dt, log_A_real, A_imag, out, L);
    } else {
        s4d_kernel<<<grid, BT>>>(Cp, log_dt, log_A_real, A_imag, out, NH, L);
    }
}

// round 14
// speedup vs baseline: 1.1193x; 1.1193x over previous
#include <cuda_runtime.h>
#include <cuda_bf16.h>
#include <cstdint>

// S4D Vandermonde kernel.
// out[h, l] = 2 * Re( sum_n Ceff[h,n] * exp(dtA[h,n] * l) ),  l in [0, L)
//
// R11: R7 structure (register resync, Chebyshev real recurrence) + software
// pipelining: pair p+1's start-state (IMAD/I2F/MUFU chain) is computed while
// pair p's fma hot loop runs, hiding the ~60cyc transcendental latency that
// previously sat serially at the head of every pair.
//   hot loop: y_{k+1} = t*y_k - d*y_{k-1},  t = 2*Re(w), d = |w|^2,
//             w = exp(dtA*2*BT);  3 packed f32x2 ops per output step per stream.
// Chunk-start phase via integer fixed-point turns (no FP64 in hot path):
//   P = round(frac(dtAim/2pi)*2^32), phase(l) = (int32)(P*l)*2pi/2^32.
// Thread t of a BT-thread block covers l = base + j*BT + t (coalesced stores).

#define BT 128   // threads per block
#define TL 32    // l-values per thread (register accumulators)
#define MAXNH 64

typedef unsigned long long u64;

__device__ __forceinline__ u64 pack2(float lo, float hi) {
    u64 d; asm("mov.b64 %0, {%1, %2};" : "=l"(d) : "f"(lo), "f"(hi)); return d;
}
__device__ __forceinline__ float2 unpack2(u64 v) {
    float2 f; asm("mov.b64 {%0, %1}, %2;" : "=f"(f.x), "=f"(f.y) : "l"(v)); return f;
}
__device__ __forceinline__ u64 mul2(u64 a, u64 b) {
    u64 d; asm("mul.rn.f32x2 %0, %1, %2;" : "=l"(d) : "l"(a), "l"(b)); return d;
}
__device__ __forceinline__ u64 add2(u64 a, u64 b) {
    u64 d; asm("add.rn.f32x2 %0, %1, %2;" : "=l"(d) : "l"(a), "l"(b)); return d;
}
__device__ __forceinline__ u64 fma2(u64 a, u64 b, u64 c) {
    u64 d; asm("fma.rn.f32x2 %0, %1, %2, %3;" : "=l"(d) : "l"(a), "l"(b), "l"(c)); return d;
}

__global__ __launch_bounds__(BT)
void s4d_kernel(const float* __restrict__ Cp,
                const float* __restrict__ log_dt,
                const float* __restrict__ log_A_real,
                const float* __restrict__ A_imag,
                float* __restrict__ out,
                int NH, int L)
{
    __shared__ float        sh_dtAre[MAXNH];
    __shared__ unsigned int sh_P[MAXNH];
    __shared__ float        sh_C2re[MAXNH], sh_C2im[MAXNH];
    __shared__ float        sh_Rre[MAXNH],  sh_Rim[MAXNH];   // step BT
    __shared__ float        sh_R2re[MAXNH], sh_R2im[MAXNH];  // step 2*BT
    __shared__ float        sh_T2[MAXNH],   sh_ND2[MAXNH];   // t = 2*R2re, -d = -|R2|^2

    const int h    = blockIdx.y;
    const int tid  = threadIdx.x;
    const int base = blockIdx.x * (BT * TL);

    // ---- per-(h,n) precompute (once per block; FP64 allowed here) ----
    if (tid < NH) {
        const int n = tid;
        const float dtv   = expf(log_dt[h]);
        const float Aim   = A_imag[h * NH + n];
        const float Are   = -expf(log_A_real[h * NH + n]);
        const float dtAre = Are * dtv;
        const float dtAim = Aim * dtv;

        float sn1, cs1; sincosf(dtAim, &sn1, &cs1);
        const float mg  = expf(dtAre);
        const float er  = mg * cs1 - 1.0f;
        const float ei  = mg * sn1;
        const float inv = 1.0f / (Are * Are + Aim * Aim);
        const float qre = (er * Are + ei * Aim) * inv;
        const float qim = (ei * Are - er * Aim) * inv;
        const float Cre = Cp[(h * NH + n) * 2 + 0];
        const float Cim = Cp[(h * NH + n) * 2 + 1];
        sh_C2re[n] = 2.0f * (Cre * qre - Cim * qim);
        sh_C2im[n] = 2.0f * (Cre * qim + Cim * qre);
        {
            double f  = (double)dtAim * 0.15915494309189535;
            double fr = f - floor(f);
            sh_P[n] = (unsigned int)(unsigned long long)(fr * 4294967296.0 + 0.5);
        }
        {
            float sp, cp2; sincosf(dtAim * (float)BT, &sp, &cp2);
            const float Rm = expf(dtAre * (float)BT);
            sh_Rre[n] = Rm * cp2;  sh_Rim[n] = Rm * sp;
        }
        {
            float sp, cp2; sincosf(dtAim * (float)(2 * BT), &sp, &cp2);
            const float Rm = expf(dtAre * (float)(2 * BT));
            sh_R2re[n] = Rm * cp2;  sh_R2im[n] = Rm * sp;
            sh_T2[n]   = 2.0f * Rm * cp2;
            sh_ND2[n]  = -expf(dtAre * (float)(4 * BT));
        }
        sh_dtAre[n] = dtAre;
    }
    __syncthreads();

    u64 acc[TL];
    #pragma unroll
    for (int j = 0; j < TL; j++) acc[j] = 0ull;

    const unsigned int l0u = (unsigned int)(base + tid);
    const float        l0f = (float)(base + tid);
    const int npairs = NH >> 1;
    const float TWO_PI_OVER_2_32 = 1.4629180792671596e-9f;

    // resync for a pair -> packed start state (se_re, se_im)
    auto resync = [&](int p, u64& re, u64& im) {
        const int nA = 2 * p, nB = 2 * p + 1;
        float thA = (float)(int)(sh_P[nA] * l0u) * TWO_PI_OVER_2_32;  // [-pi, pi)
        float thB = (float)(int)(sh_P[nB] * l0u) * TWO_PI_OVER_2_32;
        float snA, csA; __sincosf(thA, &snA, &csA);
        float snB, csB; __sincosf(thB, &snB, &csB);
        float mA = __expf(sh_dtAre[nA] * l0f);
        float mB = __expf(sh_dtAre[nB] * l0f);
        float crA = sh_C2re[nA], ciA = sh_C2im[nA];
        float crB = sh_C2re[nB], ciB = sh_C2im[nB];
        re = pack2(mA * (crA * csA - ciA * snA), mB * (crB * csB - ciB * snB));
        im = pack2(mA * (crA * snA + ciA * csA), mB * (crB * snB + ciB * csB));
    };

    // ---- software-pipelined main loop over n-pairs ----
    u64 cur_re, cur_im;
    resync(0, cur_re, cur_im);

    for (int p = 0; p < npairs; p++) {
        const int nA = 2 * p, nB = 2 * p + 1;

        // issue next pair's resync chain early (independent of hot loop below)
        u64 nxt_re = 0ull, nxt_im = 0ull;
        if (p + 1 < npairs) resync(p + 1, nxt_re, nxt_im);

        const u64 se_re = cur_re;
        const u64 se_im = cur_im;

        // odd stream start: so = se * R(BT)
        u64 rre  = pack2(sh_Rre[nA],   sh_Rre[nB]);
        u64 rim  = pack2(sh_Rim[nA],   sh_Rim[nB]);
        u64 nrim = pack2(-sh_Rim[nA],  -sh_Rim[nB]);
        u64 so_re = fma2(se_im, nrim, mul2(se_re, rre));
        u64 so_im = fma2(se_im, rre,  mul2(se_re, rim));

        // y1 per stream: Re(s * R2)
        u64 r2re  = pack2(sh_R2re[nA],  sh_R2re[nB]);
        u64 nr2im = pack2(-sh_R2im[nA], -sh_R2im[nB]);
        u64 ye0 = se_re;
        u64 ye1 = fma2(se_im, nr2im, mul2(se_re, r2re));
        u64 yo0 = so_re;
        u64 yo1 = fma2(so_im, nr2im, mul2(so_re, r2re));

        u64 t2  = pack2(sh_T2[nA],  sh_T2[nB]);
        u64 nd2 = pack2(sh_ND2[nA], sh_ND2[nB]);

        acc[0] = add2(acc[0], ye0);
        acc[1] = add2(acc[1], yo0);
        acc[2] = add2(acc[2], ye1);
        acc[3] = add2(acc[3], yo1);

        // ---- hot loop: y_{k+1} = t*y_k + (-d)*y_{k-1}; 3 packed ops/step/stream ----
        #pragma unroll
        for (int k = 2; k < TL / 2; k++) {
            u64 ye2 = fma2(t2, ye1, mul2(nd2, ye0));
            acc[2 * k] = add2(acc[2 * k], ye2);
            ye0 = ye1; ye1 = ye2;

            u64 yo2 = fma2(t2, yo1, mul2(nd2, yo0));
            acc[2 * k + 1] = add2(acc[2 * k + 1], yo2);
            yo0 = yo1; yo1 = yo2;
        }

        cur_re = nxt_re;
        cur_im = nxt_im;
    }

    // ---- coalesced epilogue ----
    float* op = out + (size_t)h * (size_t)L;
    #pragma unroll
    for (int j = 0; j < TL; j++) {
        const int l = base + j * BT + tid;
        if (l < L) {
            float2 f = unpack2(acc[j]);
            op[l] = f.x + f.y;
        }
    }
}

extern "C" void kernel_launch(void* const* d_in, const int* in_sizes, int n_in,
                              void* d_out, int out_size) {
    const float* Cp         = (const float*)d_in[0];  // (H, NH, 2)
    const float* log_dt     = (const float*)d_in[1];  // (H,)
    const float* log_A_real = (const float*)d_in[2];  // (H, NH)
    const float* A_imag     = (const float*)d_in[3];  // (H, NH)
    float* out = (float*)d_out;                       // (H, L)

    const int H  = in_sizes[1];
    const int NH = in_sizes[2] / H;
    const int L  = out_size / H;

    const int chunk = BT * TL;
    dim3 grid((L + chunk - 1) / chunk, H);
    s4d_kernel<<<grid, BT>>>(Cp, log_dt, log_A_real, A_imag, out, NH, L);
}

// round 16
// speedup vs baseline: 1.1371x; 1.0159x over previous
#include <cuda_runtime.h>
#include <cuda_bf16.h>
#include <cstdint>

// S4D Vandermonde kernel.
// out[h, l] = 2 * Re( sum_n Ceff[h,n] * exp(dtA[h,n] * l) ),  l in [0, L)
//
// R14: manual interleave of the next pair's resync INTO the unrolled hot loop.
// The k-loop is fully unrolled, so `if (k == const)` blocks constant-fold and
// place each resync micro-step (IMAD / I2F / MUFU / LDS / FMUL) in the same
// basic block as independent fma work -> ptxas must emit them interleaved,
// hiding the ~100cyc transcendental chain under the fma stream.
//   hot loop: y_{k+1} = t*y_k - d*y_{k-1},  t = 2*Re(w), d = |w|^2,
//             w = exp(dtA*2*BT);  3 packed f32x2 ops per output step per stream.
// Chunk-start phase via integer fixed-point turns (no FP64 in hot path):
//   P = round(frac(dtAim/2pi)*2^32), phase(l) = (int32)(P*l)*2pi/2^32.
// Thread t of a BT-thread block covers l = base + j*BT + t (coalesced stores).

#define BT 128   // threads per block
#define TL 32    // l-values per thread (register accumulators)
#define MAXNH 64

typedef unsigned long long u64;

__device__ __forceinline__ u64 pack2(float lo, float hi) {
    u64 d; asm("mov.b64 %0, {%1, %2};" : "=l"(d) : "f"(lo), "f"(hi)); return d;
}
__device__ __forceinline__ float2 unpack2(u64 v) {
    float2 f; asm("mov.b64 {%0, %1}, %2;" : "=f"(f.x), "=f"(f.y) : "l"(v)); return f;
}
__device__ __forceinline__ u64 mul2(u64 a, u64 b) {
    u64 d; asm("mul.rn.f32x2 %0, %1, %2;" : "=l"(d) : "l"(a), "l"(b)); return d;
}
__device__ __forceinline__ u64 add2(u64 a, u64 b) {
    u64 d; asm("add.rn.f32x2 %0, %1, %2;" : "=l"(d) : "l"(a), "l"(b)); return d;
}
__device__ __forceinline__ u64 fma2(u64 a, u64 b, u64 c) {
    u64 d; asm("fma.rn.f32x2 %0, %1, %2, %3;" : "=l"(d) : "l"(a), "l"(b), "l"(c)); return d;
}

__global__ __launch_bounds__(BT, 4)
void s4d_kernel(const float* __restrict__ Cp,
                const float* __restrict__ log_dt,
                const float* __restrict__ log_A_real,
                const float* __restrict__ A_imag,
                float* __restrict__ out,
                int NH, int L)
{
    __shared__ float        sh_dtAre[MAXNH];
    __shared__ unsigned int sh_P[MAXNH];
    __shared__ float        sh_C2re[MAXNH], sh_C2im[MAXNH];
    __shared__ float        sh_Rre[MAXNH],  sh_Rim[MAXNH];   // step BT
    __shared__ float        sh_R2re[MAXNH], sh_R2im[MAXNH];  // step 2*BT
    __shared__ float        sh_T2[MAXNH],   sh_ND2[MAXNH];   // t = 2*R2re, -d = -|R2|^2

    const int h    = blockIdx.y;
    const int tid  = threadIdx.x;
    const int base = blockIdx.x * (BT * TL);

    // ---- per-(h,n) precompute (once per block; FP64 allowed here) ----
    if (tid < NH) {
        const int n = tid;
        const float dtv   = expf(log_dt[h]);
        const float Aim   = A_imag[h * NH + n];
        const float Are   = -expf(log_A_real[h * NH + n]);
        const float dtAre = Are * dtv;
        const float dtAim = Aim * dtv;

        float sn1, cs1; sincosf(dtAim, &sn1, &cs1);
        const float mg  = expf(dtAre);
        const float er  = mg * cs1 - 1.0f;
        const float ei  = mg * sn1;
        const float inv = 1.0f / (Are * Are + Aim * Aim);
        const float qre = (er * Are + ei * Aim) * inv;
        const float qim = (ei * Are - er * Aim) * inv;
        const float Cre = Cp[(h * NH + n) * 2 + 0];
        const float Cim = Cp[(h * NH + n) * 2 + 1];
        sh_C2re[n] = 2.0f * (Cre * qre - Cim * qim);
        sh_C2im[n] = 2.0f * (Cre * qim + Cim * qre);
        {
            double f  = (double)dtAim * 0.15915494309189535;
            double fr = f - floor(f);
            sh_P[n] = (unsigned int)(unsigned long long)(fr * 4294967296.0 + 0.5);
        }
        {
            float sp, cp2; sincosf(dtAim * (float)BT, &sp, &cp2);
            const float Rm = expf(dtAre * (float)BT);
            sh_Rre[n] = Rm * cp2;  sh_Rim[n] = Rm * sp;
        }
        {
            float sp, cp2; sincosf(dtAim * (float)(2 * BT), &sp, &cp2);
            const float Rm = expf(dtAre * (float)(2 * BT));
            sh_R2re[n] = Rm * cp2;  sh_R2im[n] = Rm * sp;
            sh_T2[n]   = 2.0f * Rm * cp2;
            sh_ND2[n]  = -expf(dtAre * (float)(4 * BT));
        }
        sh_dtAre[n] = dtAre;
    }
    __syncthreads();

    u64 acc[TL];
    #pragma unroll
    for (int j = 0; j < TL; j++) acc[j] = 0ull;

    const unsigned int l0u = (unsigned int)(base + tid);
    const float        l0f = (float)(base + tid);
    const int npairs = NH >> 1;
    const float TWO_PI_OVER_2_32 = 1.4629180792671596e-9f;

    // ---- full resync for pair 0 (prologue only) ----
    u64 cur_re, cur_im;
    {
        float thA = (float)(int)(sh_P[0] * l0u) * TWO_PI_OVER_2_32;  // [-pi, pi)
        float thB = (float)(int)(sh_P[1] * l0u) * TWO_PI_OVER_2_32;
        float snA, csA; __sincosf(thA, &snA, &csA);
        float snB, csB; __sincosf(thB, &snB, &csB);
        float mA = __expf(sh_dtAre[0] * l0f);
        float mB = __expf(sh_dtAre[1] * l0f);
        float crA = sh_C2re[0], ciA = sh_C2im[0];
        float crB = sh_C2re[1], ciB = sh_C2im[1];
        cur_re = pack2(mA * (crA * csA - ciA * snA), mB * (crB * csB - ciB * snB));
        cur_im = pack2(mA * (crA * snA + ciA * csA), mB * (crB * snB + ciB * csB));
    }

    for (int p = 0; p < npairs; p++) {
        const int nA = 2 * p, nB = 2 * p + 1;
        // next pair's indices (last iteration redundantly recomputes pair p —
        // branch-free so the resync micro-steps stay in the hot basic block)
        const int pn  = (p + 1 < npairs) ? p + 1 : p;
        const int nA2 = 2 * pn, nB2 = 2 * pn + 1;

        const u64 se_re = cur_re;
        const u64 se_im = cur_im;

        // odd stream start: so = se * R(BT)
        u64 rre  = pack2(sh_Rre[nA],   sh_Rre[nB]);
        u64 rim  = pack2(sh_Rim[nA],   sh_Rim[nB]);
        u64 nrim = pack2(-sh_Rim[nA],  -sh_Rim[nB]);
        u64 so_re = fma2(se_im, nrim, mul2(se_re, rre));
        u64 so_im = fma2(se_im, rre,  mul2(se_re, rim));

        // y1 per stream: Re(s * R2)
        u64 r2re  = pack2(sh_R2re[nA],  sh_R2re[nB]);
        u64 nr2im = pack2(-sh_R2im[nA], -sh_R2im[nB]);
        u64 ye0 = se_re;
        u64 ye1 = fma2(se_im, nr2im, mul2(se_re, r2re));
        u64 yo0 = so_re;
        u64 yo1 = fma2(so_im, nr2im, mul2(so_re, r2re));

        u64 t2  = pack2(sh_T2[nA],  sh_T2[nB]);
        u64 nd2 = pack2(sh_ND2[nA], sh_ND2[nB]);

        acc[0] = add2(acc[0], ye0);
        acc[1] = add2(acc[1], yo0);
        acc[2] = add2(acc[2], ye1);
        acc[3] = add2(acc[3], yo1);

        // resync temporaries (live across unrolled iterations)
        int   iA = 0, iB = 0;
        float thA = 0.f, thB = 0.f;
        float snA = 0.f, csA = 0.f, snB = 0.f, csB = 0.f;
        float mA = 0.f, mB = 0.f;
        float crA = 0.f, ciA = 0.f, crB = 0.f, ciB = 0.f;
        float nreA = 0.f, nimA = 0.f, nreB = 0.f, nimB = 0.f;

        // ---- hot loop with interleaved next-pair resync micro-steps ----
        #pragma unroll
        for (int k = 2; k < TL / 2; k++) {
            u64 ye2 = fma2(t2, ye1, mul2(nd2, ye0));
            acc[2 * k] = add2(acc[2 * k], ye2);
            ye0 = ye1; ye1 = ye2;

            u64 yo2 = fma2(t2, yo1, mul2(nd2, yo0));
            acc[2 * k + 1] = add2(acc[2 * k + 1], yo2);
            yo0 = yo1; yo1 = yo2;

            // constant-folded after unroll: each block lands inline, branch-free
            if (k == 2)  { iA = (int)(sh_P[nA2] * l0u); iB = (int)(sh_P[nB2] * l0u); }
            if (k == 3)  { thA = (float)iA * TWO_PI_OVER_2_32;
                           thB = (float)iB * TWO_PI_OVER_2_32; }
            if (k == 4)  { __sincosf(thA, &snA, &csA); }
            if (k == 5)  { __sincosf(thB, &snB, &csB); }
            if (k == 6)  { mA = __expf(sh_dtAre[nA2] * l0f); }
            if (k == 7)  { mB = __expf(sh_dtAre[nB2] * l0f); }
            if (k == 8)  { crA = sh_C2re[nA2]; ciA = sh_C2im[nA2];
                           crB = sh_C2re[nB2]; ciB = sh_C2im[nB2]; }
            if (k == 9)  { nreA = mA * (crA * csA - ciA * snA);
                           nimA = mA * (crA * snA + ciA * csA); }
            if (k == 10) { nreB = mB * (crB * csB - ciB * snB);
                           nimB = mB * (crB * snB + ciB * csB); }
            if (k == 11) { cur_re = pack2(nreA, nreB);
                           cur_im = pack2(nimA, nimB); }
        }
    }

    // ---- coalesced epilogue ----
    float* op = out + (size_t)h * (size_t)L;
    #pragma unroll
    for (int j = 0; j < TL; j++) {
        const int l = base + j * BT + tid;
        if (l < L) {
            float2 f = unpack2(acc[j]);
            op[l] = f.x + f.y;
        }
    }
}

extern "C" void kernel_launch(void* const* d_in, const int* in_sizes, int n_in,
                              void* d_out, int out_size) {
    const float* Cp         = (const float*)d_in[0];  // (H, NH, 2)
    const float* log_dt     = (const float*)d_in[1];  // (H,)
    const float* log_A_real = (const float*)d_in[2];  // (H, NH)
    const float* A_imag     = (const float*)d_in[3];  // (H, NH)
    float* out = (float*)d_out;                       // (H, L)

    const int H  = in_sizes[1];
    const int NH = in_sizes[2] / H;
    const int L  = out_size / H;

    const int chunk = BT * TL;
    dim3 grid((L + chunk - 1) / chunk, H);
    s4d_kernel<<<grid, BT>>>(Cp, log_dt, log_A_real, A_imag, out, NH, L);
}